// round 1
// baseline (speedup 1.0000x reference)
#include <cuda_runtime.h>
#include <math.h>

// Problem constants (AttentionLayer_11776800325798)
#define NMAX   50000
#define EMAX   500000
#define TT     3
#define RR     5
#define HH     8
#define DKK    16
#define FDIM   128
#define NRH    (NMAX * RR * HH)          // 2,000,000
#define NL_CAP ((((NMAX + 31) / 32) + TT) * 32)   // 50112
#define SQRT_DK 4.0f

// ---------------- scratch (static __device__, no allocation) ----------------
__device__ float    g_k[NMAX * FDIM];
__device__ float    g_q[NMAX * FDIM];
__device__ float    g_v[NMAX * FDIM];
__device__ float    g_acc[NMAX * FDIM];
__device__ float    g_a[EMAX * HH];
__device__ unsigned g_m[NRH];
__device__ float    g_den[NRH];
__device__ int      g_nlist[NL_CAP];
__device__ int      g_cnt[TT];
__device__ int      g_cur[TT];
__device__ int      g_poff[TT + 1];

// ordered-uint encoding for float atomicMax
__device__ __forceinline__ unsigned fkey(float f) {
    unsigned b = __float_as_uint(f);
    return (b & 0x80000000u) ? ~b : (b | 0x80000000u);
}
__device__ __forceinline__ float fdecode(unsigned u) {
    unsigned b = (u & 0x80000000u) ? (u & 0x7FFFFFFFu) : ~u;
    return __uint_as_float(b);
}

// ---------------- K0: zero scratch ----------------
__global__ void zero_kernel() {
    int stride = gridDim.x * blockDim.x;
    for (int idx = blockIdx.x * blockDim.x + threadIdx.x; idx < NMAX * FDIM; idx += stride) {
        g_acc[idx] = 0.f;
        if (idx < NRH) { g_m[idx] = 0u; g_den[idx] = 0.f; }
        if (idx < NL_CAP) g_nlist[idx] = -1;
        if (idx < TT) { g_cnt[idx] = 0; g_cur[idx] = 0; }
    }
}

// ---------------- counting sort of nodes by type ----------------
__global__ void hist_kernel(const int* __restrict__ ntype, int N) {
    int i = blockIdx.x * blockDim.x + threadIdx.x;
    if (i < N) atomicAdd(&g_cnt[ntype[i]], 1);
}
__global__ void scan_kernel() {
    if (threadIdx.x == 0 && blockIdx.x == 0) {
        int o = 0;
        for (int t = 0; t < TT; t++) { g_poff[t] = o; o += ((g_cnt[t] + 31) / 32) * 32; }
        g_poff[TT] = o;
    }
}
__global__ void scatter_kernel(const int* __restrict__ ntype, int N) {
    int i = blockIdx.x * blockDim.x + threadIdx.x;
    if (i < N) {
        int t = ntype[i];
        int pos = g_poff[t] + atomicAdd(&g_cur[t], 1);
        g_nlist[pos] = i;
    }
}

// ---------------- K1: typed projections k,q,v ----------------
// One block = 32 nodes of a single type. 128 threads, thread j owns output col j.
__global__ __launch_bounds__(128) void proj_kernel(
    const float* __restrict__ x, const int* __restrict__ ntype,
    const float* __restrict__ Wk, const float* __restrict__ bk,
    const float* __restrict__ Wq, const float* __restrict__ bq,
    const float* __restrict__ Wv, const float* __restrict__ bv)
{
    __shared__ __align__(16) float xs[32][FDIM];
    __shared__ int s_nl[32];
    __shared__ int s_t;
    int j = threadIdx.x;
    int base = blockIdx.x * 32;
    if (j < 32) s_nl[j] = g_nlist[base + j];
    __syncthreads();
    if (j == 0) {
        int t = -1;
        for (int m = 0; m < 32; m++) if (s_nl[m] >= 0) { t = ntype[s_nl[m]]; break; }
        s_t = t;
    }
    #pragma unroll
    for (int m = 0; m < 32; m++) {
        int n = s_nl[m];
        xs[m][j] = (n >= 0) ? x[n * FDIM + j] : 0.f;
    }
    __syncthreads();
    if (s_t < 0) return;

#define PROJ_PASS(Wmat, Bvec, OutBuf) do {                                        \
        const float* Wt = (Wmat) + s_t * FDIM * FDIM;                             \
        float acc[32];                                                            \
        _Pragma("unroll") for (int m = 0; m < 32; m++) acc[m] = 0.f;              \
        for (int k0 = 0; k0 < FDIM; k0 += 4) {                                    \
            float w0 = Wt[(k0 + 0) * FDIM + j];                                   \
            float w1 = Wt[(k0 + 1) * FDIM + j];                                   \
            float w2 = Wt[(k0 + 2) * FDIM + j];                                   \
            float w3 = Wt[(k0 + 3) * FDIM + j];                                   \
            _Pragma("unroll") for (int m = 0; m < 32; m++) {                      \
                float4 xv = *(const float4*)&xs[m][k0];                           \
                acc[m] = fmaf(xv.x, w0, fmaf(xv.y, w1,                            \
                         fmaf(xv.z, w2, fmaf(xv.w, w3, acc[m]))));                \
            }                                                                     \
        }                                                                         \
        float bb = (Bvec)[s_t * FDIM + j];                                        \
        _Pragma("unroll") for (int m = 0; m < 32; m++) {                          \
            int n = s_nl[m];                                                      \
            if (n >= 0) (OutBuf)[n * FDIM + j] = acc[m] + bb;                     \
        }                                                                         \
    } while (0)

    PROJ_PASS(Wk, bk, g_k);
    PROJ_PASS(Wq, bq, g_q);
    PROJ_PASS(Wv, bv, g_v);
#undef PROJ_PASS
}

// ---------------- K2: edge scores + segment max ----------------
// 8 lanes per edge (one per head). rel_att staged in SMEM (40KB).
__global__ __launch_bounds__(256) void score_kernel(
    const int* __restrict__ src, const int* __restrict__ dst,
    const int* __restrict__ etype,
    const float* __restrict__ rel_pri, const float* __restrict__ rel_att, int E)
{
    __shared__ __align__(16) float s_att[RR * HH * DKK * DKK];  // 10240 floats
    __shared__ float s_pri[RR * HH];
    for (int i = threadIdx.x; i < RR * HH * DKK * DKK; i += 256) s_att[i] = rel_att[i];
    if (threadIdx.x < RR * HH) s_pri[threadIdx.x] = rel_pri[threadIdx.x];
    __syncthreads();

    int grp = threadIdx.x >> 3;
    int lane = threadIdx.x & 7;
    for (int e = blockIdx.x * 32 + grp; e < E; e += gridDim.x * 32) {
        int s = src[e], d = dst[e], r = etype[e];
        const float4* kp = (const float4*)(g_k + s * FDIM + lane * DKK);
        const float4* qp = (const float4*)(g_q + d * FDIM + lane * DKK);
        float kr[16], qr[16];
        #pragma unroll
        for (int i = 0; i < 4; i++) {
            float4 kv = kp[i]; kr[i*4+0]=kv.x; kr[i*4+1]=kv.y; kr[i*4+2]=kv.z; kr[i*4+3]=kv.w;
            float4 qv = qp[i]; qr[i*4+0]=qv.x; qr[i*4+1]=qv.y; qr[i*4+2]=qv.z; qr[i*4+3]=qv.w;
        }
        const float4* A4 = (const float4*)(s_att + (r * HH + lane) * (DKK * DKK));
        float a = 0.f;
        #pragma unroll
        for (int c = 0; c < 16; c++) {
            float4 a0 = A4[c*4+0], a1 = A4[c*4+1], a2 = A4[c*4+2], a3 = A4[c*4+3];
            float t = a0.x*qr[0]+a0.y*qr[1]+a0.z*qr[2]+a0.w*qr[3]
                    + a1.x*qr[4]+a1.y*qr[5]+a1.z*qr[6]+a1.w*qr[7]
                    + a2.x*qr[8]+a2.y*qr[9]+a2.z*qr[10]+a2.w*qr[11]
                    + a3.x*qr[12]+a3.y*qr[13]+a3.z*qr[14]+a3.w*qr[15];
            a = fmaf(kr[c], t, a);
        }
        a *= s_pri[r * HH + lane] * (1.0f / SQRT_DK);
        g_a[e * HH + lane] = a;
        atomicMax(&g_m[(d * RR + r) * HH + lane], fkey(a));
    }
}

// ---------------- K3: exp + segment denom ----------------
__global__ __launch_bounds__(256) void expsum_kernel(
    const int* __restrict__ dst, const int* __restrict__ etype, int E)
{
    int idx = blockIdx.x * blockDim.x + threadIdx.x;
    if (idx >= E * HH) return;
    int e = idx >> 3, h = idx & 7;
    int mi = (dst[e] * RR + etype[e]) * HH + h;
    float m = fdecode(g_m[mi]);
    float p = __expf(g_a[idx] - m);
    g_a[idx] = p;
    atomicAdd(&g_den[mi], p);
}

// ---------------- K4: weighted message aggregation ----------------
__global__ __launch_bounds__(256) void agg_kernel(
    const int* __restrict__ src, const int* __restrict__ dst,
    const int* __restrict__ etype, const float* __restrict__ rel_msg, int E)
{
    __shared__ __align__(16) float s_msg[RR * HH * DKK * DKK];
    for (int i = threadIdx.x; i < RR * HH * DKK * DKK; i += 256) s_msg[i] = rel_msg[i];
    __syncthreads();

    int grp = threadIdx.x >> 3;
    int lane = threadIdx.x & 7;
    for (int e = blockIdx.x * 32 + grp; e < E; e += gridDim.x * 32) {
        int s = src[e], d = dst[e], r = etype[e];
        float p = g_a[e * HH + lane];
        float den = g_den[(d * RR + r) * HH + lane];
        float attw = p / den;
        const float4* vp = (const float4*)(g_v + s * FDIM + lane * DKK);
        float vr[16];
        #pragma unroll
        for (int i = 0; i < 4; i++) {
            float4 vv = vp[i]; vr[i*4+0]=vv.x; vr[i*4+1]=vv.y; vr[i*4+2]=vv.z; vr[i*4+3]=vv.w;
        }
        const float4* M4 = (const float4*)(s_msg + (r * HH + lane) * (DKK * DKK));
        float o[16];
        #pragma unroll
        for (int i = 0; i < 16; i++) o[i] = 0.f;
        #pragma unroll
        for (int c = 0; c < 16; c++) {
            float vc = vr[c];
            float4 m0 = M4[c*4+0], m1 = M4[c*4+1], m2 = M4[c*4+2], m3 = M4[c*4+3];
            o[0]  = fmaf(vc, m0.x, o[0]);  o[1]  = fmaf(vc, m0.y, o[1]);
            o[2]  = fmaf(vc, m0.z, o[2]);  o[3]  = fmaf(vc, m0.w, o[3]);
            o[4]  = fmaf(vc, m1.x, o[4]);  o[5]  = fmaf(vc, m1.y, o[5]);
            o[6]  = fmaf(vc, m1.z, o[6]);  o[7]  = fmaf(vc, m1.w, o[7]);
            o[8]  = fmaf(vc, m2.x, o[8]);  o[9]  = fmaf(vc, m2.y, o[9]);
            o[10] = fmaf(vc, m2.z, o[10]); o[11] = fmaf(vc, m2.w, o[11]);
            o[12] = fmaf(vc, m3.x, o[12]); o[13] = fmaf(vc, m3.y, o[13]);
            o[14] = fmaf(vc, m3.z, o[14]); o[15] = fmaf(vc, m3.w, o[15]);
        }
        float* dp = g_acc + d * FDIM + lane * DKK;
        #pragma unroll
        for (int i = 0; i < 4; i++) {
            float4 add = make_float4(attw*o[i*4+0], attw*o[i*4+1], attw*o[i*4+2], attw*o[i*4+3]);
            atomicAdd((float4*)(dp + i * 4), add);   // sm_90+ vector reduction
        }
    }
}

// ---------------- K5: mean-over-etypes, Wa proj, skip blend, per-type LN ----------------
__global__ __launch_bounds__(128) void final_kernel(
    const float* __restrict__ x, const int* __restrict__ ntype,
    const float* __restrict__ Wa, const float* __restrict__ ba,
    const float* __restrict__ skipv,
    const float* __restrict__ ln_g, const float* __restrict__ ln_b,
    float* __restrict__ out)
{
    __shared__ __align__(16) float ts[32][FDIM];
    __shared__ int s_nl[32];
    __shared__ int s_t;
    __shared__ float scp[32];
    int j = threadIdx.x;
    int base = blockIdx.x * 32;
    if (j < 32) s_nl[j] = g_nlist[base + j];
    __syncthreads();
    if (j == 0) {
        int t = -1;
        for (int m = 0; m < 32; m++) if (s_nl[m] >= 0) { t = ntype[s_nl[m]]; break; }
        s_t = t;
    }
    if (j < 32) {
        int n = s_nl[j];
        float inv = 1.f;
        if (n >= 0) {
            int cp = 0;
            for (int r = 0; r < RR; r++) cp += (g_den[(n * RR + r) * HH] > 0.f) ? 1 : 0;
            if (cp < 1) cp = 1;
            inv = 1.f / (float)cp;
        }
        scp[j] = inv;
    }
    __syncthreads();
    if (s_t < 0) return;
    #pragma unroll
    for (int m = 0; m < 32; m++) {
        int n = s_nl[m];
        ts[m][j] = (n >= 0) ? g_acc[n * FDIM + j] * scp[m] : 0.f;
    }
    __syncthreads();

    const float* Wt = Wa + s_t * FDIM * FDIM;
    float acc[32];
    #pragma unroll
    for (int m = 0; m < 32; m++) acc[m] = 0.f;
    for (int k0 = 0; k0 < FDIM; k0 += 4) {
        float w0 = Wt[(k0 + 0) * FDIM + j];
        float w1 = Wt[(k0 + 1) * FDIM + j];
        float w2 = Wt[(k0 + 2) * FDIM + j];
        float w3 = Wt[(k0 + 3) * FDIM + j];
        #pragma unroll
        for (int m = 0; m < 32; m++) {
            float4 xv = *(const float4*)&ts[m][k0];
            acc[m] = fmaf(xv.x, w0, fmaf(xv.y, w1, fmaf(xv.z, w2, fmaf(xv.w, w3, acc[m]))));
        }
    }
    __syncthreads();  // all ts reads done before overwrite

    float bb = ba[s_t * FDIM + j];
    float alpha = 1.f / (1.f + __expf(-skipv[s_t]));
    #pragma unroll
    for (int m = 0; m < 32; m++) {
        int n = s_nl[m];
        if (n >= 0) {
            float xv = x[n * FDIM + j];
            ts[m][j] = (acc[m] + bb) * alpha + xv * (1.f - alpha);
        } else {
            ts[m][j] = 0.f;
        }
    }
    __syncthreads();

    // LayerNorm: warp w handles 8 nodes, 32 lanes reduce 128 elements
    int w = j >> 5, lane = j & 31;
    float g0 = ln_g[s_t * FDIM + lane],      b0 = ln_b[s_t * FDIM + lane];
    float g1 = ln_g[s_t * FDIM + lane + 32], b1 = ln_b[s_t * FDIM + lane + 32];
    float g2 = ln_g[s_t * FDIM + lane + 64], b2 = ln_b[s_t * FDIM + lane + 64];
    float g3 = ln_g[s_t * FDIM + lane + 96], b3 = ln_b[s_t * FDIM + lane + 96];
    for (int q = 0; q < 8; q++) {
        int m = w * 8 + q;
        int n = s_nl[m];
        if (n < 0) continue;
        float v0 = ts[m][lane], v1 = ts[m][lane + 32], v2 = ts[m][lane + 64], v3 = ts[m][lane + 96];
        float s = v0 + v1 + v2 + v3;
        float s2 = v0*v0 + v1*v1 + v2*v2 + v3*v3;
        #pragma unroll
        for (int o = 16; o; o >>= 1) {
            s  += __shfl_xor_sync(0xFFFFFFFFu, s,  o);
            s2 += __shfl_xor_sync(0xFFFFFFFFu, s2, o);
        }
        float mu = s * (1.f / 128.f);
        float var = s2 * (1.f / 128.f) - mu * mu;
        float rstd = rsqrtf(var + 1e-5f);
        out[n * FDIM + lane]      = (v0 - mu) * rstd * g0 + b0;
        out[n * FDIM + lane + 32] = (v1 - mu) * rstd * g1 + b1;
        out[n * FDIM + lane + 64] = (v2 - mu) * rstd * g2 + b2;
        out[n * FDIM + lane + 96] = (v3 - mu) * rstd * g3 + b3;
    }
}

// ---------------- launch ----------------
extern "C" void kernel_launch(void* const* d_in, const int* in_sizes, int n_in,
                              void* d_out, int out_size)
{
    const float* x       = (const float*)d_in[0];
    const int*   ntype   = (const int*)  d_in[1];
    const int*   src     = (const int*)  d_in[2];
    const int*   dst     = (const int*)  d_in[3];
    const int*   etype   = (const int*)  d_in[4];
    const float* Wk      = (const float*)d_in[5];
    const float* bk      = (const float*)d_in[6];
    const float* Wq      = (const float*)d_in[7];
    const float* bq      = (const float*)d_in[8];
    const float* Wv      = (const float*)d_in[9];
    const float* bv      = (const float*)d_in[10];
    const float* Wa      = (const float*)d_in[11];
    const float* ba      = (const float*)d_in[12];
    const float* rel_pri = (const float*)d_in[13];
    const float* rel_att = (const float*)d_in[14];
    const float* rel_msg = (const float*)d_in[15];
    const float* skipv   = (const float*)d_in[16];
    const float* ln_g    = (const float*)d_in[17];
    const float* ln_b    = (const float*)d_in[18];
    float* out = (float*)d_out;

    const int N = in_sizes[1];
    const int E = in_sizes[2];
    const int NTILES = (N + TT * 32 + 31) / 32;

    zero_kernel<<<4096, 256>>>();
    hist_kernel<<<(N + 255) / 256, 256>>>(ntype, N);
    scan_kernel<<<1, 32>>>();
    scatter_kernel<<<(N + 255) / 256, 256>>>(ntype, N);
    proj_kernel<<<NTILES, 128>>>(x, ntype, Wk, bk, Wq, bq, Wv, bv);
    score_kernel<<<1536, 256>>>(src, dst, etype, rel_pri, rel_att, E);
    expsum_kernel<<<(E * HH + 255) / 256, 256>>>(dst, etype, E);
    agg_kernel<<<1536, 256>>>(src, dst, etype, rel_msg, E);
    final_kernel<<<NTILES, 128>>>(x, ntype, Wa, ba, skipv, ln_g, ln_b, out);
}

// round 2
// speedup vs baseline: 3.3506x; 3.3506x over previous
#include <cuda_runtime.h>
#include <math.h>

// Problem constants (AttentionLayer_11776800325798)
#define NMAX   50000
#define EMAX   500000
#define TT     3
#define RR     5
#define HH     8
#define DKK    16
#define FDIM   128
#define NRH    (NMAX * RR * HH)          // 2,000,000
#define NL_CAP ((((NMAX + 31) / 32) + TT) * 32)   // 50112
#define SQRT_DK 4.0f
#define MATPAD 272                        // 256 + 16 floats: stride mod 32 banks = 16

// ---------------- scratch (static __device__, no allocation) ----------------
__device__ float    g_k[NMAX * FDIM];
__device__ float    g_q[NMAX * FDIM];
__device__ float    g_v[NMAX * FDIM];
__device__ float    g_acc[NMAX * FDIM];
__device__ float    g_a[EMAX * HH];
__device__ unsigned g_m[NRH];
__device__ float    g_den[NRH];
__device__ int      g_nlist[NL_CAP];
__device__ int      g_cnt[TT];
__device__ int      g_cur[TT];
__device__ int      g_poff[TT + 1];

// ordered-uint encoding for float atomicMax
__device__ __forceinline__ unsigned fkey(float f) {
    unsigned b = __float_as_uint(f);
    return (b & 0x80000000u) ? ~b : (b | 0x80000000u);
}
__device__ __forceinline__ float fdecode(unsigned u) {
    unsigned b = (u & 0x80000000u) ? (u & 0x7FFFFFFFu) : ~u;
    return __uint_as_float(b);
}

// ---------------- K0: zero scratch ----------------
__global__ void zero_kernel() {
    int stride = gridDim.x * blockDim.x;
    for (int idx = blockIdx.x * blockDim.x + threadIdx.x; idx < NMAX * FDIM; idx += stride) {
        g_acc[idx] = 0.f;
        if (idx < NRH) { g_m[idx] = 0u; g_den[idx] = 0.f; }
        if (idx < NL_CAP) g_nlist[idx] = -1;
        if (idx < TT) { g_cnt[idx] = 0; g_cur[idx] = 0; }
    }
}

// ---------------- counting sort of nodes by type (warp-aggregated atomics) ----------------
__global__ void hist_kernel(const int* __restrict__ ntype, int N) {
    int i = blockIdx.x * blockDim.x + threadIdx.x;
    int t = (i < N) ? ntype[i] : -1;
    #pragma unroll
    for (int tt = 0; tt < TT; tt++) {
        unsigned mask = __ballot_sync(0xFFFFFFFFu, t == tt);
        if (t == tt) {
            int lane = threadIdx.x & 31;
            int leader = __ffs(mask) - 1;
            if (lane == leader) atomicAdd(&g_cnt[tt], __popc(mask));
        }
    }
}
__global__ void scan_kernel() {
    if (threadIdx.x == 0 && blockIdx.x == 0) {
        int o = 0;
        for (int t = 0; t < TT; t++) { g_poff[t] = o; o += ((g_cnt[t] + 31) / 32) * 32; }
        g_poff[TT] = o;
    }
}
__global__ void scatter_kernel(const int* __restrict__ ntype, int N) {
    int i = blockIdx.x * blockDim.x + threadIdx.x;
    int t = (i < N) ? ntype[i] : -1;
    #pragma unroll
    for (int tt = 0; tt < TT; tt++) {
        unsigned mask = __ballot_sync(0xFFFFFFFFu, t == tt);
        if (t == tt) {
            int lane = threadIdx.x & 31;
            int leader = __ffs(mask) - 1;
            int rank = __popc(mask & ((1u << lane) - 1));
            int base = 0;
            if (lane == leader) base = atomicAdd(&g_cur[tt], __popc(mask));
            base = __shfl_sync(mask, base, leader);
            g_nlist[g_poff[tt] + base + rank] = i;
        }
    }
}

// ---------------- K1: typed projections k,q,v ----------------
// One block = 32 nodes of a single type. 128 threads, thread j owns output col j.
__global__ __launch_bounds__(128) void proj_kernel(
    const float* __restrict__ x, const int* __restrict__ ntype,
    const float* __restrict__ Wk, const float* __restrict__ bk,
    const float* __restrict__ Wq, const float* __restrict__ bq,
    const float* __restrict__ Wv, const float* __restrict__ bv)
{
    __shared__ __align__(16) float xs[32][FDIM];
    __shared__ int s_nl[32];
    __shared__ int s_t;
    int j = threadIdx.x;
    int base = blockIdx.x * 32;
    if (j < 32) s_nl[j] = g_nlist[base + j];
    __syncthreads();
    if (j == 0) {
        int t = -1;
        for (int m = 0; m < 32; m++) if (s_nl[m] >= 0) { t = ntype[s_nl[m]]; break; }
        s_t = t;
    }
    #pragma unroll
    for (int m = 0; m < 32; m++) {
        int n = s_nl[m];
        xs[m][j] = (n >= 0) ? x[n * FDIM + j] : 0.f;
    }
    __syncthreads();
    if (s_t < 0) return;

#define PROJ_PASS(Wmat, Bvec, OutBuf) do {                                        \
        const float* Wt = (Wmat) + s_t * FDIM * FDIM;                             \
        float acc[32];                                                            \
        _Pragma("unroll") for (int m = 0; m < 32; m++) acc[m] = 0.f;              \
        for (int k0 = 0; k0 < FDIM; k0 += 4) {                                    \
            float w0 = Wt[(k0 + 0) * FDIM + j];                                   \
            float w1 = Wt[(k0 + 1) * FDIM + j];                                   \
            float w2 = Wt[(k0 + 2) * FDIM + j];                                   \
            float w3 = Wt[(k0 + 3) * FDIM + j];                                   \
            _Pragma("unroll") for (int m = 0; m < 32; m++) {                      \
                float4 xv = *(const float4*)&xs[m][k0];                           \
                acc[m] = fmaf(xv.x, w0, fmaf(xv.y, w1,                            \
                         fmaf(xv.z, w2, fmaf(xv.w, w3, acc[m]))));                \
            }                                                                     \
        }                                                                         \
        float bb = (Bvec)[s_t * FDIM + j];                                        \
        _Pragma("unroll") for (int m = 0; m < 32; m++) {                          \
            int n = s_nl[m];                                                      \
            if (n >= 0) (OutBuf)[n * FDIM + j] = acc[m] + bb;                     \
        }                                                                         \
    } while (0)

    PROJ_PASS(Wk, bk, g_k);
    PROJ_PASS(Wq, bq, g_q);
    PROJ_PASS(Wv, bv, g_v);
#undef PROJ_PASS
}

// ---------------- K2: edge scores + segment max ----------------
// Warp per edge. lane = h*4 + q: head h (0..7), f-quad q (0..3).
// SMEM matrices padded to MATPAD=272 floats -> conflict-free LDS.128:
// bank(lane) = 16h + 16d + 4q mod 32 -> each quarter-warp covers all 32 banks once.
__global__ __launch_bounds__(256) void score_kernel(
    const int* __restrict__ src, const int* __restrict__ dst,
    const int* __restrict__ etype,
    const float* __restrict__ rel_pri, const float* __restrict__ rel_att, int E)
{
    __shared__ __align__(16) float s_att[RR * HH * MATPAD];
    __shared__ float s_pri[RR * HH];
    for (int idx = threadIdx.x; idx < RR * HH * DKK * DKK; idx += 256) {
        int mat = idx >> 8, inner = idx & 255;
        s_att[mat * MATPAD + inner] = rel_att[idx];
    }
    if (threadIdx.x < RR * HH) s_pri[threadIdx.x] = rel_pri[threadIdx.x];
    __syncthreads();

    int warp = threadIdx.x >> 5;
    int lane = threadIdx.x & 31;
    int h = lane >> 2, qq = lane & 3;
    for (int e = blockIdx.x * 8 + warp; e < E; e += gridDim.x * 8) {
        int s = src[e], d = dst[e], r = etype[e];
        // k row of head h (all 4 lanes of a head load same addr -> broadcast)
        const float4* kp = (const float4*)(g_k + s * FDIM + h * DKK);
        float kr[16];
        #pragma unroll
        for (int i = 0; i < 4; i++) {
            float4 kv = kp[i];
            kr[i*4+0]=kv.x; kr[i*4+1]=kv.y; kr[i*4+2]=kv.z; kr[i*4+3]=kv.w;
        }
        // q quad for this lane (coalesced 512B per warp)
        float4 qv = *(const float4*)(g_q + d * FDIM + h * DKK + qq * 4);
        const float* A = s_att + (r * HH + h) * MATPAD + qq * 4;
        float4 t = make_float4(0.f, 0.f, 0.f, 0.f);
        #pragma unroll
        for (int dd = 0; dd < 16; dd++) {
            float4 av = *(const float4*)(A + dd * DKK);
            float kc = kr[dd];
            t.x = fmaf(kc, av.x, t.x);
            t.y = fmaf(kc, av.y, t.y);
            t.z = fmaf(kc, av.z, t.z);
            t.w = fmaf(kc, av.w, t.w);
        }
        float sc = t.x*qv.x + t.y*qv.y + t.z*qv.z + t.w*qv.w;
        sc += __shfl_xor_sync(0xFFFFFFFFu, sc, 1);
        sc += __shfl_xor_sync(0xFFFFFFFFu, sc, 2);
        sc *= s_pri[r * HH + h] * (1.0f / SQRT_DK);
        if (qq == 0) {
            g_a[e * HH + h] = sc;
            atomicMax(&g_m[(d * RR + r) * HH + h], fkey(sc));
        }
    }
}

// ---------------- K3: exp + segment denom ----------------
__global__ __launch_bounds__(256) void expsum_kernel(
    const int* __restrict__ dst, const int* __restrict__ etype, int E)
{
    int idx = blockIdx.x * blockDim.x + threadIdx.x;
    if (idx >= E * HH) return;
    int e = idx >> 3, hh = idx & 7;
    int mi = (dst[e] * RR + etype[e]) * HH + hh;
    float m = fdecode(g_m[mi]);
    float p = __expf(g_a[idx] - m);
    g_a[idx] = p;
    atomicAdd(&g_den[mi], p);
}

// ---------------- K4: weighted message aggregation ----------------
// Warp per edge, same (h, q) lane mapping and padded SMEM as score_kernel.
__global__ __launch_bounds__(256) void agg_kernel(
    const int* __restrict__ src, const int* __restrict__ dst,
    const int* __restrict__ etype, const float* __restrict__ rel_msg, int E)
{
    __shared__ __align__(16) float s_msg[RR * HH * MATPAD];
    for (int idx = threadIdx.x; idx < RR * HH * DKK * DKK; idx += 256) {
        int mat = idx >> 8, inner = idx & 255;
        s_msg[mat * MATPAD + inner] = rel_msg[idx];
    }
    __syncthreads();

    int warp = threadIdx.x >> 5;
    int lane = threadIdx.x & 31;
    int h = lane >> 2, qq = lane & 3;
    for (int e = blockIdx.x * 8 + warp; e < E; e += gridDim.x * 8) {
        int s = src[e], d = dst[e], r = etype[e];
        float p = g_a[e * HH + h];
        float den = g_den[(d * RR + r) * HH + h];
        float attw = p / den;
        const float4* vp = (const float4*)(g_v + s * FDIM + h * DKK);
        float vr[16];
        #pragma unroll
        for (int i = 0; i < 4; i++) {
            float4 vv = vp[i];
            vr[i*4+0]=vv.x; vr[i*4+1]=vv.y; vr[i*4+2]=vv.z; vr[i*4+3]=vv.w;
        }
        const float* M = s_msg + (r * HH + h) * MATPAD + qq * 4;
        float4 o = make_float4(0.f, 0.f, 0.f, 0.f);
        #pragma unroll
        for (int dd = 0; dd < 16; dd++) {
            float4 mv = *(const float4*)(M + dd * DKK);
            float vc = vr[dd];
            o.x = fmaf(vc, mv.x, o.x);
            o.y = fmaf(vc, mv.y, o.y);
            o.z = fmaf(vc, mv.z, o.z);
            o.w = fmaf(vc, mv.w, o.w);
        }
        float4 add = make_float4(attw*o.x, attw*o.y, attw*o.z, attw*o.w);
        atomicAdd((float4*)(g_acc + d * FDIM + h * DKK + qq * 4), add);
    }
}

// ---------------- K5: mean-over-etypes, Wa proj, skip blend, per-type LN ----------------
__global__ __launch_bounds__(128) void final_kernel(
    const float* __restrict__ x, const int* __restrict__ ntype,
    const float* __restrict__ Wa, const float* __restrict__ ba,
    const float* __restrict__ skipv,
    const float* __restrict__ ln_g, const float* __restrict__ ln_b,
    float* __restrict__ out)
{
    __shared__ __align__(16) float ts[32][FDIM];
    __shared__ int s_nl[32];
    __shared__ int s_t;
    __shared__ float scp[32];
    int j = threadIdx.x;
    int base = blockIdx.x * 32;
    if (j < 32) s_nl[j] = g_nlist[base + j];
    __syncthreads();
    if (j == 0) {
        int t = -1;
        for (int m = 0; m < 32; m++) if (s_nl[m] >= 0) { t = ntype[s_nl[m]]; break; }
        s_t = t;
    }
    if (j < 32) {
        int n = s_nl[j];
        float inv = 1.f;
        if (n >= 0) {
            int cp = 0;
            for (int r = 0; r < RR; r++) cp += (g_den[(n * RR + r) * HH] > 0.f) ? 1 : 0;
            if (cp < 1) cp = 1;
            inv = 1.f / (float)cp;
        }
        scp[j] = inv;
    }
    __syncthreads();
    if (s_t < 0) return;
    #pragma unroll
    for (int m = 0; m < 32; m++) {
        int n = s_nl[m];
        ts[m][j] = (n >= 0) ? g_acc[n * FDIM + j] * scp[m] : 0.f;
    }
    __syncthreads();

    const float* Wt = Wa + s_t * FDIM * FDIM;
    float acc[32];
    #pragma unroll
    for (int m = 0; m < 32; m++) acc[m] = 0.f;
    for (int k0 = 0; k0 < FDIM; k0 += 4) {
        float w0 = Wt[(k0 + 0) * FDIM + j];
        float w1 = Wt[(k0 + 1) * FDIM + j];
        float w2 = Wt[(k0 + 2) * FDIM + j];
        float w3 = Wt[(k0 + 3) * FDIM + j];
        #pragma unroll
        for (int m = 0; m < 32; m++) {
            float4 xv = *(const float4*)&ts[m][k0];
            acc[m] = fmaf(xv.x, w0, fmaf(xv.y, w1, fmaf(xv.z, w2, fmaf(xv.w, w3, acc[m]))));
        }
    }
    __syncthreads();  // all ts reads done before overwrite

    float bb = ba[s_t * FDIM + j];
    float alpha = 1.f / (1.f + __expf(-skipv[s_t]));
    #pragma unroll
    for (int m = 0; m < 32; m++) {
        int n = s_nl[m];
        if (n >= 0) {
            float xv = x[n * FDIM + j];
            ts[m][j] = (acc[m] + bb) * alpha + xv * (1.f - alpha);
        } else {
            ts[m][j] = 0.f;
        }
    }
    __syncthreads();

    // LayerNorm: warp w handles 8 nodes, 32 lanes reduce 128 elements
    int w = j >> 5, lane = j & 31;
    float g0 = ln_g[s_t * FDIM + lane],      b0 = ln_b[s_t * FDIM + lane];
    float g1 = ln_g[s_t * FDIM + lane + 32], b1 = ln_b[s_t * FDIM + lane + 32];
    float g2 = ln_g[s_t * FDIM + lane + 64], b2 = ln_b[s_t * FDIM + lane + 64];
    float g3 = ln_g[s_t * FDIM + lane + 96], b3 = ln_b[s_t * FDIM + lane + 96];
    for (int q = 0; q < 8; q++) {
        int m = w * 8 + q;
        int n = s_nl[m];
        if (n < 0) continue;
        float v0 = ts[m][lane], v1 = ts[m][lane + 32], v2 = ts[m][lane + 64], v3 = ts[m][lane + 96];
        float s = v0 + v1 + v2 + v3;
        float s2 = v0*v0 + v1*v1 + v2*v2 + v3*v3;
        #pragma unroll
        for (int o = 16; o; o >>= 1) {
            s  += __shfl_xor_sync(0xFFFFFFFFu, s,  o);
            s2 += __shfl_xor_sync(0xFFFFFFFFu, s2, o);
        }
        float mu = s * (1.f / 128.f);
        float var = s2 * (1.f / 128.f) - mu * mu;
        float rstd = rsqrtf(var + 1e-5f);
        out[n * FDIM + lane]      = (v0 - mu) * rstd * g0 + b0;
        out[n * FDIM + lane + 32] = (v1 - mu) * rstd * g1 + b1;
        out[n * FDIM + lane + 64] = (v2 - mu) * rstd * g2 + b2;
        out[n * FDIM + lane + 96] = (v3 - mu) * rstd * g3 + b3;
    }
}

// ---------------- launch ----------------
extern "C" void kernel_launch(void* const* d_in, const int* in_sizes, int n_in,
                              void* d_out, int out_size)
{
    const float* x       = (const float*)d_in[0];
    const int*   ntype   = (const int*)  d_in[1];
    const int*   src     = (const int*)  d_in[2];
    const int*   dst     = (const int*)  d_in[3];
    const int*   etype   = (const int*)  d_in[4];
    const float* Wk      = (const float*)d_in[5];
    const float* bk      = (const float*)d_in[6];
    const float* Wq      = (const float*)d_in[7];
    const float* bq      = (const float*)d_in[8];
    const float* Wv      = (const float*)d_in[9];
    const float* bv      = (const float*)d_in[10];
    const float* Wa      = (const float*)d_in[11];
    const float* ba      = (const float*)d_in[12];
    const float* rel_pri = (const float*)d_in[13];
    const float* rel_att = (const float*)d_in[14];
    const float* rel_msg = (const float*)d_in[15];
    const float* skipv   = (const float*)d_in[16];
    const float* ln_g    = (const float*)d_in[17];
    const float* ln_b    = (const float*)d_in[18];
    float* out = (float*)d_out;

    const int N = in_sizes[1];
    const int E = in_sizes[2];
    const int NTILES = (N + TT * 32 + 31) / 32;

    zero_kernel<<<4096, 256>>>();
    hist_kernel<<<(N + 255) / 256, 256>>>(ntype, N);
    scan_kernel<<<1, 32>>>();
    scatter_kernel<<<(N + 255) / 256, 256>>>(ntype, N);
    proj_kernel<<<NTILES, 128>>>(x, ntype, Wk, bk, Wq, bq, Wv, bv);
    score_kernel<<<2048, 256>>>(src, dst, etype, rel_pri, rel_att, E);
    expsum_kernel<<<(E * HH + 255) / 256, 256>>>(dst, etype, E);
    agg_kernel<<<2048, 256>>>(src, dst, etype, rel_msg, E);
    final_kernel<<<NTILES, 128>>>(x, ntype, Wa, ba, skipv, ln_g, ln_b, out);
}

// round 5
// speedup vs baseline: 3.7584x; 1.1217x over previous
#include <cuda_runtime.h>
#include <cuda_bf16.h>
#include <mma.h>
#include <stdint.h>
#include <math.h>

using namespace nvcuda;

// Problem constants (AttentionLayer_11776800325798)
#define NMAX   50000
#define EMAX   500000
#define TT     3
#define RR     5
#define HH     8
#define DKK    16
#define FDIM   128
#define NRH    (NMAX * RR * HH)                      // 2,000,000
#define NL_CAP (((NMAX / 128) + TT + 1) * 128)       // 50432, 128-padded per type
#define SQRT_DK 4.0f
#define MATPAD 272                                   // SMEM matrix stride (floats), mod 32 = 16
#define LDA 136                                      // bf16 elems per row (128 + 8 pad)
#define LDB 136

// ---------------- scratch (static __device__, no allocation) ----------------
__device__ float    g_k[NMAX * FDIM];
__device__ float    g_q[NMAX * FDIM];
__device__ float    g_v[NMAX * FDIM];
__device__ float    g_acc[NMAX * FDIM];
__device__ float    g_a[EMAX * HH];
__device__ float    g_den[NRH];
__device__ int      g_nlist[NL_CAP];
__device__ int      g_cnt[TT];
__device__ int      g_cur[TT];
__device__ int      g_poff[TT + 1];

// fp32 -> bf16 hi + bf16 lo (packed pairs)
__device__ __forceinline__ uint32_t bfsplit(float a, float b, uint32_t& lo) {
    __nv_bfloat162 h = __floats2bfloat162_rn(a, b);
    float ra = a - __bfloat162float(h.x);
    float rb = b - __bfloat162float(h.y);
    __nv_bfloat162 l = __floats2bfloat162_rn(ra, rb);
    lo = *reinterpret_cast<uint32_t*>(&l);
    return *reinterpret_cast<uint32_t*>(&h);
}

// ============================================================================
// K0: zero scratch
// ============================================================================
__global__ void zero_kernel() {
    int stride = gridDim.x * blockDim.x;
    for (int idx = blockIdx.x * blockDim.x + threadIdx.x; idx < NMAX * FDIM; idx += stride) {
        g_acc[idx] = 0.f;
        if (idx < NRH) g_den[idx] = 0.f;
        if (idx < NL_CAP) g_nlist[idx] = -1;
        if (idx < TT) { g_cnt[idx] = 0; g_cur[idx] = 0; }
    }
}

// ---------------- counting sort of nodes by type (warp-aggregated atomics) ----------------
__global__ void hist_kernel(const int* __restrict__ ntype, int N) {
    int i = blockIdx.x * blockDim.x + threadIdx.x;
    int t = (i < N) ? ntype[i] : -1;
    #pragma unroll
    for (int tt = 0; tt < TT; tt++) {
        unsigned mask = __ballot_sync(0xFFFFFFFFu, t == tt);
        if (t == tt) {
            int lane = threadIdx.x & 31;
            if (lane == __ffs(mask) - 1) atomicAdd(&g_cnt[tt], __popc(mask));
        }
    }
}
__global__ void scan_kernel() {
    if (threadIdx.x == 0 && blockIdx.x == 0) {
        int o = 0;
        for (int t = 0; t < TT; t++) { g_poff[t] = o; o += ((g_cnt[t] + 127) / 128) * 128; }
        g_poff[TT] = o;
    }
}
__global__ void scatter_kernel(const int* __restrict__ ntype, int N) {
    int i = blockIdx.x * blockDim.x + threadIdx.x;
    int t = (i < N) ? ntype[i] : -1;
    #pragma unroll
    for (int tt = 0; tt < TT; tt++) {
        unsigned mask = __ballot_sync(0xFFFFFFFFu, t == tt);
        if (t == tt) {
            int lane = threadIdx.x & 31;
            int leader = __ffs(mask) - 1;
            int rank = __popc(mask & ((1u << lane) - 1));
            int base = 0;
            if (lane == leader) base = atomicAdd(&g_cur[tt], __popc(mask));
            base = __shfl_sync(mask, base, leader);
            g_nlist[g_poff[tt] + base + rank] = i;
        }
    }
}

// ============================================================================
// K1: typed projections via wmma bf16 split (fp32-accurate)
// One block = 128 nodes of one type, 256 threads (8 warps).
// dyn SMEM: A_hi|A_lo|B_hi|B_lo bf16 [128][136] each.
// Warp w computes rows [w*16, w*16+16) x all 128 cols.
// D = A_hi*B_hi + A_hi*B_lo + A_lo*B_hi  (lo*lo term ~2^-32, negligible)
// ============================================================================
__global__ __launch_bounds__(256) void proj_wmma_kernel(
    const float* __restrict__ x, const int* __restrict__ ntype,
    const float* __restrict__ Wk, const float* __restrict__ bk,
    const float* __restrict__ Wq, const float* __restrict__ bq,
    const float* __restrict__ Wv, const float* __restrict__ bv)
{
    extern __shared__ __align__(16) char dynsm[];
    __nv_bfloat16* Ah = (__nv_bfloat16*)dynsm;
    __nv_bfloat16* Al = Ah + 128 * LDA;
    __nv_bfloat16* Bh = Al + 128 * LDA;
    __nv_bfloat16* Bl = Bh + 128 * LDB;
    __shared__ int s_nl[128];
    __shared__ int s_t;
    __shared__ __align__(16) float stg[8][16][24];

    int tid = threadIdx.x, w = tid >> 5, lane = tid & 31;
    if (tid < 128) s_nl[tid] = g_nlist[blockIdx.x * 128 + tid];
    __syncthreads();
    if (tid == 0) {
        int t = -1;
        for (int m = 0; m < 128; m++) if (s_nl[m] >= 0) { t = ntype[s_nl[m]]; break; }
        s_t = t;
    }
    __syncthreads();
    if (s_t < 0) return;

    // ---- stage A: gather x rows, split into bf16 hi/lo ----
    for (int idx = tid; idx < 128 * 32; idx += 256) {
        int m = idx >> 5, c = (idx & 31) * 4;
        int n = s_nl[m];
        float4 f = (n >= 0) ? *(const float4*)(x + (size_t)n * FDIM + c)
                            : make_float4(0.f, 0.f, 0.f, 0.f);
        uint32_t l0, l1;
        uint32_t h0 = bfsplit(f.x, f.y, l0), h1 = bfsplit(f.z, f.w, l1);
        *(uint32_t*)(Ah + m * LDA + c)     = h0;
        *(uint32_t*)(Ah + m * LDA + c + 2) = h1;
        *(uint32_t*)(Al + m * LDA + c)     = l0;
        *(uint32_t*)(Al + m * LDA + c + 2) = l1;
    }

    int row_m = w * 16;
    int r = lane >> 1, c0 = (lane & 1) * 8;
    int gr = s_nl[row_m + r];

    for (int set = 0; set < 3; set++) {
        // ---- stage B: W[t] straight from global, split hi/lo ----
        const float* W    = ((set == 0) ? Wk : (set == 1) ? Wq : Wv) + s_t * FDIM * FDIM;
        const float* bias = ((set == 0) ? bk : (set == 1) ? bq : bv) + s_t * FDIM;
        for (int idx = tid; idx < 128 * 32; idx += 256) {
            int kk = idx >> 5, c = (idx & 31) * 4;
            float4 f = *(const float4*)(W + kk * FDIM + c);
            uint32_t l0, l1;
            uint32_t h0 = bfsplit(f.x, f.y, l0), h1 = bfsplit(f.z, f.w, l1);
            *(uint32_t*)(Bh + kk * LDB + c)     = h0;
            *(uint32_t*)(Bh + kk * LDB + c + 2) = h1;
            *(uint32_t*)(Bl + kk * LDB + c)     = l0;
            *(uint32_t*)(Bl + kk * LDB + c + 2) = l1;
        }
        __syncthreads();   // A (first set) + B visible

        wmma::fragment<wmma::accumulator, 16, 16, 16, float> acc[8];
        #pragma unroll
        for (int ni = 0; ni < 8; ni++) wmma::fill_fragment(acc[ni], 0.f);
        for (int k = 0; k < 8; k++) {
            wmma::fragment<wmma::matrix_a, 16, 16, 16, __nv_bfloat16, wmma::row_major> ah, al;
            wmma::load_matrix_sync(ah, Ah + row_m * LDA + k * 16, LDA);
            wmma::load_matrix_sync(al, Al + row_m * LDA + k * 16, LDA);
            #pragma unroll
            for (int ni = 0; ni < 8; ni++) {
                wmma::fragment<wmma::matrix_b, 16, 16, 16, __nv_bfloat16, wmma::row_major> bh, bl;
                wmma::load_matrix_sync(bh, Bh + (k * 16) * LDB + ni * 16, LDB);
                wmma::load_matrix_sync(bl, Bl + (k * 16) * LDB + ni * 16, LDB);
                wmma::mma_sync(acc[ni], ah, bh, acc[ni]);
                wmma::mma_sync(acc[ni], ah, bl, acc[ni]);
                wmma::mma_sync(acc[ni], al, bh, acc[ni]);
            }
        }

        // ---- epilogue: per-warp staging, add bias, scatter-store ----
        float* ob = (set == 0) ? g_k : (set == 1) ? g_q : g_v;
        for (int ni = 0; ni < 8; ni++) {
            wmma::store_matrix_sync(&stg[w][0][0], acc[ni], 24, wmma::mem_row_major);
            __syncwarp();
            if (gr >= 0) {
                int col = ni * 16 + c0;
                float4 v0 = *(float4*)&stg[w][r][c0];
                float4 v1 = *(float4*)&stg[w][r][c0 + 4];
                v0.x += bias[col + 0]; v0.y += bias[col + 1];
                v0.z += bias[col + 2]; v0.w += bias[col + 3];
                v1.x += bias[col + 4]; v1.y += bias[col + 5];
                v1.z += bias[col + 6]; v1.w += bias[col + 7];
                *(float4*)(ob + (size_t)gr * FDIM + col)     = v0;
                *(float4*)(ob + (size_t)gr * FDIM + col + 4) = v1;
            }
            __syncwarp();
        }
        __syncthreads();   // all B reads done before next set overwrites
    }
}

// ============================================================================
// K2: edge scores + exp + segment denom (no max pass: scores analytically small)
// Warp per edge. lane = h*4 + q. SMEM matrices padded (MATPAD) -> conflict-free.
// ============================================================================
__global__ __launch_bounds__(256) void score_kernel(
    const int* __restrict__ src, const int* __restrict__ dst,
    const int* __restrict__ etype,
    const float* __restrict__ rel_pri, const float* __restrict__ rel_att, int E) {
    __shared__ __align__(16) float s_att[RR * HH * MATPAD];
    __shared__ float s_pri[RR * HH];
    for (int idx = threadIdx.x; idx < RR * HH * DKK * DKK; idx += 256) {
        int mat = idx >> 8, inner = idx & 255;
        s_att[mat * MATPAD + inner] = rel_att[idx];
    }
    if (threadIdx.x < RR * HH) s_pri[threadIdx.x] = rel_pri[threadIdx.x];
    __syncthreads();

    int warp = threadIdx.x >> 5;
    int lane = threadIdx.x & 31;
    int h = lane >> 2, qq = lane & 3;
    for (int e = blockIdx.x * 8 + warp; e < E; e += gridDim.x * 8) {
        int s = src[e], d = dst[e], r = etype[e];
        const float4* kp = (const float4*)(g_k + s * FDIM + h * DKK);
        float kr[16];
        #pragma unroll
        for (int i = 0; i < 4; i++) {
            float4 kv = kp[i];
            kr[i*4+0]=kv.x; kr[i*4+1]=kv.y; kr[i*4+2]=kv.z; kr[i*4+3]=kv.w;
        }
        float4 qv = *(const float4*)(g_q + d * FDIM + h * DKK + qq * 4);
        const float* A = s_att + (r * HH + h) * MATPAD + qq * 4;
        float4 t = make_float4(0.f, 0.f, 0.f, 0.f);
        #pragma unroll
        for (int dd = 0; dd < 16; dd++) {
            float4 av = *(const float4*)(A + dd * DKK);
            float kc = kr[dd];
            t.x = fmaf(kc, av.x, t.x);
            t.y = fmaf(kc, av.y, t.y);
            t.z = fmaf(kc, av.z, t.z);
            t.w = fmaf(kc, av.w, t.w);
        }
        float sc = t.x*qv.x + t.y*qv.y + t.z*qv.z + t.w*qv.w;
        sc += __shfl_xor_sync(0xFFFFFFFFu, sc, 1);
        sc += __shfl_xor_sync(0xFFFFFFFFu, sc, 2);
        sc *= s_pri[r * HH + h] * (1.0f / SQRT_DK);
        if (qq == 0) {
            float p = __expf(sc);
            g_a[e * HH + h] = p;
            atomicAdd(&g_den[(d * RR + r) * HH + h], p);
        }
    }
}

// ============================================================================
// K4: weighted message aggregation
// ============================================================================
__global__ __launch_bounds__(256) void agg_kernel(
    const int* __restrict__ src, const int* __restrict__ dst,
    const int* __restrict__ etype, const float* __restrict__ rel_msg, int E) {
    __shared__ __align__(16) float s_msg[RR * HH * MATPAD];
    for (int idx = threadIdx.x; idx < RR * HH * DKK * DKK; idx += 256) {
        int mat = idx >> 8, inner = idx & 255;
        s_msg[mat * MATPAD + inner] = rel_msg[idx];
    }
    __syncthreads();

    int warp = threadIdx.x >> 5;
    int lane = threadIdx.x & 31;
    int h = lane >> 2, qq = lane & 3;
    for (int e = blockIdx.x * 8 + warp; e < E; e += gridDim.x * 8) {
        int s = src[e], d = dst[e], r = etype[e];
        float p = g_a[e * HH + h];
        float den = g_den[(d * RR + r) * HH + h];
        float attw = p / den;
        const float4* vp = (const float4*)(g_v + s * FDIM + h * DKK);
        float vr[16];
        #pragma unroll
        for (int i = 0; i < 4; i++) {
            float4 vv = vp[i];
            vr[i*4+0]=vv.x; vr[i*4+1]=vv.y; vr[i*4+2]=vv.z; vr[i*4+3]=vv.w;
        }
        const float* M = s_msg + (r * HH + h) * MATPAD + qq * 4;
        float4 o = make_float4(0.f, 0.f, 0.f, 0.f);
        #pragma unroll
        for (int dd = 0; dd < 16; dd++) {
            float4 mv = *(const float4*)(M + dd * DKK);
            float vc = vr[dd];
            o.x = fmaf(vc, mv.x, o.x);
            o.y = fmaf(vc, mv.y, o.y);
            o.z = fmaf(vc, mv.z, o.z);
            o.w = fmaf(vc, mv.w, o.w);
        }
        float4 add = make_float4(attw*o.x, attw*o.y, attw*o.z, attw*o.w);
        atomicAdd((float4*)(g_acc + d * FDIM + h * DKK + qq * 4), add);
    }
}

// ============================================================================
// K5: mean-over-etypes, Wa proj, skip blend, per-type LN
// ============================================================================
__global__ __launch_bounds__(128) void final_kernel(
    const float* __restrict__ x, const int* __restrict__ ntype,
    const float* __restrict__ Wa, const float* __restrict__ ba,
    const float* __restrict__ skipv,
    const float* __restrict__ ln_g, const float* __restrict__ ln_b,
    float* __restrict__ out) {
    __shared__ __align__(16) float ts[32][FDIM];
    __shared__ int s_nl[32];
    __shared__ int s_t;
    __shared__ float scp[32];
    int j = threadIdx.x;
    int base = blockIdx.x * 32;
    if (j < 32) s_nl[j] = g_nlist[base + j];
    __syncthreads();
    if (j == 0) {
        int t = -1;
        for (int m = 0; m < 32; m++) if (s_nl[m] >= 0) { t = ntype[s_nl[m]]; break; }
        s_t = t;
    }
    if (j < 32) {
        int n = s_nl[j];
        float inv = 1.f;
        if (n >= 0) {
            int cp = 0;
            for (int r = 0; r < RR; r++) cp += (g_den[(n * RR + r) * HH] > 0.f) ? 1 : 0;
            if (cp < 1) cp = 1;
            inv = 1.f / (float)cp;
        }
        scp[j] = inv;
    }
    __syncthreads();
    if (s_t < 0) return;
    #pragma unroll
    for (int m = 0; m < 32; m++) {
        int n = s_nl[m];
        ts[m][j] = (n >= 0) ? g_acc[n * FDIM + j] * scp[m] : 0.f;
    }
    __syncthreads();

    const float* Wt = Wa + s_t * FDIM * FDIM;
    float acc[32];
    #pragma unroll
    for (int m = 0; m < 32; m++) acc[m] = 0.f;
    for (int k0 = 0; k0 < FDIM; k0 += 4) {
        float w0 = Wt[(k0 + 0) * FDIM + j];
        float w1 = Wt[(k0 + 1) * FDIM + j];
        float w2 = Wt[(k0 + 2) * FDIM + j];
        float w3 = Wt[(k0 + 3) * FDIM + j];
        #pragma unroll
        for (int m = 0; m < 32; m++) {
            float4 xv = *(const float4*)&ts[m][k0];
            acc[m] = fmaf(xv.x, w0, fmaf(xv.y, w1, fmaf(xv.z, w2, fmaf(xv.w, w3, acc[m]))));
        }
    }
    __syncthreads();

    float bb = ba[s_t * FDIM + j];
    float alpha = 1.f / (1.f + __expf(-skipv[s_t]));
    #pragma unroll
    for (int m = 0; m < 32; m++) {
        int n = s_nl[m];
        if (n >= 0) {
            float xv = x[n * FDIM + j];
            ts[m][j] = (acc[m] + bb) * alpha + xv * (1.f - alpha);
        } else {
            ts[m][j] = 0.f;
        }
    }
    __syncthreads();

    int w = j >> 5, lane = j & 31;
    float g0 = ln_g[s_t * FDIM + lane],      b0 = ln_b[s_t * FDIM + lane];
    float g1 = ln_g[s_t * FDIM + lane + 32], b1 = ln_b[s_t * FDIM + lane + 32];
    float g2 = ln_g[s_t * FDIM + lane + 64], b2 = ln_b[s_t * FDIM + lane + 64];
    float g3 = ln_g[s_t * FDIM + lane + 96], b3 = ln_b[s_t * FDIM + lane + 96];
    for (int q = 0; q < 8; q++) {
        int m = w * 8 + q;
        int n = s_nl[m];
        if (n < 0) continue;
        float v0 = ts[m][lane], v1 = ts[m][lane + 32], v2 = ts[m][lane + 64], v3 = ts[m][lane + 96];
        float s = v0 + v1 + v2 + v3;
        float s2 = v0*v0 + v1*v1 + v2*v2 + v3*v3;
        #pragma unroll
        for (int o = 16; o; o >>= 1) {
            s  += __shfl_xor_sync(0xFFFFFFFFu, s,  o);
            s2 += __shfl_xor_sync(0xFFFFFFFFu, s2, o);
        }
        float mu = s * (1.f / 128.f);
        float var = s2 * (1.f / 128.f) - mu * mu;
        float rstd = rsqrtf(var + 1e-5f);
        out[n * FDIM + lane]      = (v0 - mu) * rstd * g0 + b0;
        out[n * FDIM + lane + 32] = (v1 - mu) * rstd * g1 + b1;
        out[n * FDIM + lane + 64] = (v2 - mu) * rstd * g2 + b2;
        out[n * FDIM + lane + 96] = (v3 - mu) * rstd * g3 + b3;
    }
}

// ---------------- launch ----------------
extern "C" void kernel_launch(void* const* d_in, const int* in_sizes, int n_in,
                              void* d_out, int out_size) {
    const float* x       = (const float*)d_in[0];
    const int*   ntype   = (const int*)  d_in[1];
    const int*   src     = (const int*)  d_in[2];
    const int*   dst     = (const int*)  d_in[3];
    const int*   etype   = (const int*)  d_in[4];
    const float* Wk      = (const float*)d_in[5];
    const float* bk      = (const float*)d_in[6];
    const float* Wq      = (const float*)d_in[7];
    const float* bq      = (const float*)d_in[8];
    const float* Wv      = (const float*)d_in[9];
    const float* bv      = (const float*)d_in[10];
    const float* Wa      = (const float*)d_in[11];
    const float* ba      = (const float*)d_in[12];
    const float* rel_pri = (const float*)d_in[13];
    const float* rel_att = (const float*)d_in[14];
    const float* rel_msg = (const float*)d_in[15];
    const float* skipv   = (const float*)d_in[16];
    const float* ln_g    = (const float*)d_in[17];
    const float* ln_b    = (const float*)d_in[18];
    float* out = (float*)d_out;

    const int N = in_sizes[1];
    const int E = in_sizes[2];
    const int PROJ_SMEM = 4 * 128 * LDA * 2;   // A_hi|A_lo|B_hi|B_lo bf16

    cudaFuncSetAttribute(proj_wmma_kernel, cudaFuncAttributeMaxDynamicSharedMemorySize, PROJ_SMEM);

    zero_kernel<<<4096, 256>>>();
    hist_kernel<<<(N + 255) / 256, 256>>>(ntype, N);
    scan_kernel<<<1, 32>>>();
    scatter_kernel<<<(N + 255) / 256, 256>>>(ntype, N);
    proj_wmma_kernel<<<NL_CAP / 128, 256, PROJ_SMEM>>>(x, ntype, Wk, bk, Wq, bq, Wv, bv);
    score_kernel<<<2048, 256>>>(src, dst, etype, rel_pri, rel_att, E);
    agg_kernel<<<2048, 256>>>(src, dst, etype, rel_msg, E);
    final_kernel<<<NL_CAP / 32, 128>>>(x, ntype, Wa, ba, skipv, ln_g, ln_b, out);
}